// round 15
// baseline (speedup 1.0000x reference)
#include <cuda_runtime.h>
#include <cuda_bf16.h>

#define NN 100000
#define EE 1600000

// Scratch (__device__ globals — no allocation allowed)
__device__ float4 g_t[NN * 8];     // ts = (h @ W) * dinv[row] (fp32 payload)
__device__ float4 g_agg[NN * 8];   // accumulator, seeded with ts (self loop)
__device__ int    g_degi[NN];      // edge count per dst; static zero-init;
                                   // reset to 0 at the end of k_post2 so every
                                   // executed call starts from a clean state
                                   // (graph capture does not execute kernels).

// ---------------------------------------------------------------------------
// deg count over destinations (int RED, no return)
__global__ void k_deg(const int* __restrict__ dst, int E) {
    int e = blockIdx.x * blockDim.x + threadIdx.x;
    if (e < E) atomicAdd(&g_degi[dst[e]], 1);
}

// ---------------------------------------------------------------------------
// GEMM: T[row] = (X[row] @ W) * dinv[row], written to BOTH g_t and g_agg
// (g_agg seed = self-loop term).  dinv = rsqrt(degi + 1).
// 4 threads per row, 8 output cols each (4 packed f32x2 accumulators).
// x-row LDGs front-batched before the weight-smem fill + barrier.
//   Layer 1: X = input x, Wa = W1 [32x32], Wb = null, bias = null.
//   Layer 2: X = null => row input = relu(dinv*g_agg[row] + bias) computed
//            inline after the barrier (fused post1); Wa = Wmu, Wb = Wlv.
__global__ void k_gemm(const float4* __restrict__ X,
                       const float* __restrict__ Wa,
                       const float* __restrict__ Wb,
                       const float* __restrict__ bias,
                       int n) {
    __shared__ __align__(16) unsigned long long Ws[32][16];
    __shared__ float bs[32];
    int tid = threadIdx.x;
    int gid = blockIdx.x * blockDim.x + tid;
    int row = gid >> 2;
    int cg  = gid & 3;                       // column group: cols 8cg..8cg+7
    bool alive = (row < n);
    int rrow = alive ? row : 0;              // clamp: keep loads in-bounds,
                                             // all threads reach the barrier

    // ---- front-batched row + degree loads (overlap smem prologue) ----
    const float4* xr = (X != nullptr) ? (X + (size_t)rrow * 8)
                                      : (g_agg + (size_t)rrow * 8);
    float4 xv0 = xr[0], xv1 = xr[1], xv2 = xr[2], xv3 = xr[3];
    float4 xv4 = xr[4], xv5 = xr[5], xv6 = xr[6], xv7 = xr[7];
    int dgi = g_degi[rrow];

    // ---- stage W (packed f32x2 pairs) + bias into smem ----
    for (int idx = tid; idx < 512; idx += blockDim.x) {
        int k  = idx >> 4;
        int cp = idx & 15;
        int c0 = cp * 2;
        float v0, v1;
        if (Wb == nullptr) {                 // layer 1: W1 [32x32]
            v0 = Wa[k * 32 + c0];
            v1 = Wa[k * 32 + c0 + 1];
        } else if (c0 < 16) {                // layer 2 cols 0-15: Wmu [32x16]
            v0 = Wa[k * 16 + c0];
            v1 = Wa[k * 16 + c0 + 1];
        } else {                             // layer 2 cols 16-31: Wlv [32x16]
            v0 = Wb[k * 16 + (c0 - 16)];
            v1 = Wb[k * 16 + (c0 - 15)];
        }
        unsigned long long p;
        asm("mov.b64 %0, {%1,%2};" : "=l"(p) : "f"(v0), "f"(v1));
        Ws[k][cp] = p;
    }
    if (tid < 32) bs[tid] = (bias != nullptr) ? bias[tid] : 0.0f;
    __syncthreads();

    if (!alive) return;

    float di = rsqrtf((float)dgi + 1.0f);    // +1 self loop

    float x[32];
    {
        float4 t;
        t = xv0; x[0]=t.x; x[1]=t.y; x[2]=t.z; x[3]=t.w;
        t = xv1; x[4]=t.x; x[5]=t.y; x[6]=t.z; x[7]=t.w;
        t = xv2; x[8]=t.x; x[9]=t.y; x[10]=t.z; x[11]=t.w;
        t = xv3; x[12]=t.x; x[13]=t.y; x[14]=t.z; x[15]=t.w;
        t = xv4; x[16]=t.x; x[17]=t.y; x[18]=t.z; x[19]=t.w;
        t = xv5; x[20]=t.x; x[21]=t.y; x[22]=t.z; x[23]=t.w;
        t = xv6; x[24]=t.x; x[25]=t.y; x[26]=t.z; x[27]=t.w;
        t = xv7; x[28]=t.x; x[29]=t.y; x[30]=t.z; x[31]=t.w;
    }
    if (X == nullptr) {                      // fused post1: relu(di*agg + b1)
#pragma unroll
        for (int j = 0; j < 32; j++)
            x[j] = fmaxf(fmaf(di, x[j], bs[j]), 0.0f);
    }

    unsigned long long acc[4];
#pragma unroll
    for (int j = 0; j < 4; j++) acc[j] = 0ull;

    int cpb = cg * 4;
#pragma unroll
    for (int k = 0; k < 32; k++) {
        unsigned long long xk;
        asm("mov.b64 %0, {%1,%1};" : "=l"(xk) : "f"(x[k]));
        ulonglong2 w0 = *reinterpret_cast<const ulonglong2*>(&Ws[k][cpb]);
        ulonglong2 w1 = *reinterpret_cast<const ulonglong2*>(&Ws[k][cpb + 2]);
        asm("fma.rn.f32x2 %0, %1, %2, %0;" : "+l"(acc[0]) : "l"(xk), "l"(w0.x));
        asm("fma.rn.f32x2 %0, %1, %2, %0;" : "+l"(acc[1]) : "l"(xk), "l"(w0.y));
        asm("fma.rn.f32x2 %0, %1, %2, %0;" : "+l"(acc[2]) : "l"(xk), "l"(w1.x));
        asm("fma.rn.f32x2 %0, %1, %2, %0;" : "+l"(acc[3]) : "l"(xk), "l"(w1.y));
    }

    unsigned long long d2;
    asm("mov.b64 %0, {%1,%1};" : "=l"(d2) : "f"(di));
    float o[8];
#pragma unroll
    for (int j = 0; j < 4; j++) {
        asm("mul.rn.f32x2 %0, %0, %1;" : "+l"(acc[j]) : "l"(d2));
        asm("mov.b64 {%0,%1}, %2;"
            : "=f"(o[2 * j]), "=f"(o[2 * j + 1]) : "l"(acc[j]));
    }

    float4 r0 = make_float4(o[0], o[1], o[2], o[3]);
    float4 r1 = make_float4(o[4], o[5], o[6], o[7]);
    size_t base = (size_t)row * 8 + cg * 2;
    g_t[base]       = r0;
    g_t[base + 1]   = r1;
    g_agg[base]     = r0;   // self-loop seed
    g_agg[base + 1] = r1;
}

// ---------------------------------------------------------------------------
// AGG[dst] += T[src].
// Warp owns 32 edges: indices front-loaded (2 coalesced LDG wavefronts per
// 32 edges), SHFL-distributed (no L1tex wavefront cost). 8 independent
// iterations x 4 edges x 8 lanes; lanes 8k..8k+7 cover one edge's full 128B
// row (coalesced gather + RED.128).
__global__ void k_scatter(const int* __restrict__ src,
                          const int* __restrict__ dst, int E) {
    int warp = (blockIdx.x * blockDim.x + threadIdx.x) >> 5;
    int lane = threadIdx.x & 31;
    int base = warp * 32;
    if (base >= E) return;

    int e = base + lane;
    int sreg = (e < E) ? __ldg(&src[e]) : 0;
    int dreg = (e < E) ? __ldg(&dst[e]) : 0;

    int c   = lane & 7;      // channel quad within row
    int sub = lane >> 3;     // which of 4 edges this iteration

    if (base + 32 <= E) {
#pragma unroll
        for (int it = 0; it < 8; it++) {
            int eloc = it * 4 + sub;
            int s = __shfl_sync(0xffffffff, sreg, eloc);
            int d = __shfl_sync(0xffffffff, dreg, eloc);
            float4 v = g_t[(size_t)s * 8 + c];
            float4* p = g_agg + (size_t)d * 8 + c;
            asm volatile("red.global.add.v4.f32 [%0], {%1,%2,%3,%4};"
                         :: "l"(p), "f"(v.x), "f"(v.y), "f"(v.z), "f"(v.w)
                         : "memory");
        }
    } else {
#pragma unroll
        for (int it = 0; it < 8; it++) {
            int eloc = it * 4 + sub;
            int s = __shfl_sync(0xffffffff, sreg, eloc);
            int d = __shfl_sync(0xffffffff, dreg, eloc);
            if (base + eloc < E) {
                float4 v = g_t[(size_t)s * 8 + c];
                float4* p = g_agg + (size_t)d * 8 + c;
                asm volatile("red.global.add.v4.f32 [%0], {%1,%2,%3,%4};"
                             :: "l"(p), "f"(v.x), "f"(v.y), "f"(v.z), "f"(v.w)
                             : "memory");
            }
        }
    }
}

// ---------------------------------------------------------------------------
// final: mu -> out[0:N*16], logvar -> out[N*16:]
// out = dinv * agg + bias   (agg already contains self-loop term).
// Also resets g_degi for the next graph replay (after its last use here).
__global__ void k_post2(const float* __restrict__ bmu,
                        const float* __restrict__ blv,
                        float* __restrict__ out, int n) {
    int gid = blockIdx.x * blockDim.x + threadIdx.x;
    int i = gid >> 3;
    if (i >= n) return;
    int c = gid & 7;
    int dgi = g_degi[i];
    float di = rsqrtf((float)dgi + 1.0f);
    if (c == 0) g_degi[i] = 0;               // reset for next replay
    float4 a = g_agg[(size_t)i * 8 + c];
    float4 r;
    if (c < 4) {
        float4 bb = ((const float4*)bmu)[c];
        r.x = fmaf(di, a.x, bb.x);
        r.y = fmaf(di, a.y, bb.y);
        r.z = fmaf(di, a.z, bb.z);
        r.w = fmaf(di, a.w, bb.w);
        ((float4*)out)[(size_t)i * 4 + c] = r;
    } else {
        float4 bb = ((const float4*)blv)[c - 4];
        r.x = fmaf(di, a.x, bb.x);
        r.y = fmaf(di, a.y, bb.y);
        r.z = fmaf(di, a.z, bb.z);
        r.w = fmaf(di, a.w, bb.w);
        ((float4*)(out + (size_t)n * 16))[(size_t)i * 4 + (c - 4)] = r;
    }
}

// ---------------------------------------------------------------------------
extern "C" void kernel_launch(void* const* d_in, const int* in_sizes, int n_in,
                              void* d_out, int out_size) {
    const float* x   = (const float*)d_in[0];
    const int*   ei  = (const int*)d_in[1];
    const float* W1  = (const float*)d_in[2];
    const float* b1  = (const float*)d_in[3];
    const float* Wmu = (const float*)d_in[4];
    const float* bmu = (const float*)d_in[5];
    const float* Wlv = (const float*)d_in[6];
    const float* blv = (const float*)d_in[7];
    float* out = (float*)d_out;

    int N = in_sizes[0] / 32;
    int E = in_sizes[1] / 2;
    const int* src = ei;          // edge_index row 0
    const int* dst = ei + E;      // edge_index row 1

    const int TB = 256;
    int gE  = (E + TB - 1) / TB;
    int gN4 = (int)(((long long)N * 4 + TB - 1) / TB);   // gemm: 4 thr/row
    int gN8 = (int)(((long long)N * 8 + TB - 1) / TB);
    int gEw = (int)(((long long)E + TB - 1) / TB);       // 32 edges per warp

    // degrees (g_degi is zero at entry: static init on first call, reset by
    // the previous replay's k_post2 afterwards; capture does not execute)
    k_deg<<<gE, TB>>>(dst, E);

    // layer 1: t1 -> g_t, g_agg (seeded); scatter adds neighbor terms
    k_gemm   <<<gN4, TB>>>((const float4*)x, W1, nullptr, nullptr, N);
    k_scatter<<<gEw, TB>>>(src, dst, E);

    // layer 2: fused relu(dinv*agg + b1) -> GEMM(mu|lv) -> re-seed agg
    k_gemm   <<<gN4, TB>>>(nullptr, Wmu, Wlv, b1, N);
    k_scatter<<<gEw, TB>>>(src, dst, E);

    // final bias + dinv scale, split mu / logvar; resets g_degi
    k_post2<<<gN8, TB>>>(bmu, blv, out, N);
}

// round 16
// speedup vs baseline: 1.0855x; 1.0855x over previous
#include <cuda_runtime.h>
#include <cuda_fp16.h>
#include <cuda_bf16.h>

#define NN 100000
#define EE 1600000

// Scratch (__device__ globals — no allocation allowed)
// g_t16: message values in fp16 (gather payload) — 32 halves (64B) per row,
// stored as 8 x uint2 (4 halves each).
__device__ uint2  g_t16[NN * 8];
__device__ float4 g_agg[NN * 8];   // fp32 accumulator, seeded with self-loop ts
__device__ float  g_degf[NN];      // degree (float, includes +1 self loop)

// ---------------------------------------------------------------------------
// deg = 1 (self loop)
__global__ void k_init(int n) {
    int i = blockIdx.x * blockDim.x + threadIdx.x;
    if (i < n) g_degf[i] = 1.0f;
}

// deg count over destinations (plain RED, no return)
__global__ void k_deg(const int* __restrict__ dst, int E) {
    int e = blockIdx.x * blockDim.x + threadIdx.x;
    if (e < E) atomicAdd(&g_degf[dst[e]], 1.0f);
}

// ---------------------------------------------------------------------------
// GEMM: T[row] = (X[row] @ W) * dinv[row].
//   -> g_agg  (fp32, self-loop seed, full precision)
//   -> g_t16  (fp16, gather payload for the scatter)
// 4 threads/row, 8 cols each (4 packed f32x2 accumulators); x-row LDGs
// front-batched before the smem prologue.
//   Layer 1: X = x, Wa = W1 [32x32], Wb = null, bias = null.
//   Layer 2: X = null => row = relu(dinv*g_agg[row] + bias) (fused post1);
//            Wa = Wmu, Wb = Wlv (16+16 cols).
__global__ void k_gemm(const float4* __restrict__ X,
                       const float* __restrict__ Wa,
                       const float* __restrict__ Wb,
                       const float* __restrict__ bias,
                       int n) {
    __shared__ __align__(16) unsigned long long Ws[32][16];
    __shared__ float bs[32];
    int tid = threadIdx.x;
    int gid = blockIdx.x * blockDim.x + tid;
    int row = gid >> 2;
    int cg  = gid & 3;
    bool alive = (row < n);
    int rrow = alive ? row : 0;

    // front-batched row + degree loads (overlap smem prologue)
    const float4* xr = (X != nullptr) ? (X + (size_t)rrow * 8)
                                      : (g_agg + (size_t)rrow * 8);
    float4 xv0 = xr[0], xv1 = xr[1], xv2 = xr[2], xv3 = xr[3];
    float4 xv4 = xr[4], xv5 = xr[5], xv6 = xr[6], xv7 = xr[7];
    float dg = g_degf[rrow];

    // stage W (packed f32x2 pairs) + bias into smem
    for (int idx = tid; idx < 512; idx += blockDim.x) {
        int k  = idx >> 4;
        int cp = idx & 15;
        int c0 = cp * 2;
        float v0, v1;
        if (Wb == nullptr) {                 // layer 1: W1 [32x32]
            v0 = Wa[k * 32 + c0];
            v1 = Wa[k * 32 + c0 + 1];
        } else if (c0 < 16) {                // layer 2 cols 0-15: Wmu
            v0 = Wa[k * 16 + c0];
            v1 = Wa[k * 16 + c0 + 1];
        } else {                             // layer 2 cols 16-31: Wlv
            v0 = Wb[k * 16 + (c0 - 16)];
            v1 = Wb[k * 16 + (c0 - 15)];
        }
        unsigned long long p;
        asm("mov.b64 %0, {%1,%2};" : "=l"(p) : "f"(v0), "f"(v1));
        Ws[k][cp] = p;
    }
    if (tid < 32) bs[tid] = (bias != nullptr) ? bias[tid] : 0.0f;
    __syncthreads();

    if (!alive) return;

    float di = rsqrtf(dg);

    float x[32];
    {
        float4 t;
        t = xv0; x[0]=t.x; x[1]=t.y; x[2]=t.z; x[3]=t.w;
        t = xv1; x[4]=t.x; x[5]=t.y; x[6]=t.z; x[7]=t.w;
        t = xv2; x[8]=t.x; x[9]=t.y; x[10]=t.z; x[11]=t.w;
        t = xv3; x[12]=t.x; x[13]=t.y; x[14]=t.z; x[15]=t.w;
        t = xv4; x[16]=t.x; x[17]=t.y; x[18]=t.z; x[19]=t.w;
        t = xv5; x[20]=t.x; x[21]=t.y; x[22]=t.z; x[23]=t.w;
        t = xv6; x[24]=t.x; x[25]=t.y; x[26]=t.z; x[27]=t.w;
        t = xv7; x[28]=t.x; x[29]=t.y; x[30]=t.z; x[31]=t.w;
    }
    if (X == nullptr) {                      // fused post1: relu(di*agg + b1)
#pragma unroll
        for (int j = 0; j < 32; j++)
            x[j] = fmaxf(fmaf(di, x[j], bs[j]), 0.0f);
    }

    unsigned long long acc[4];
#pragma unroll
    for (int j = 0; j < 4; j++) acc[j] = 0ull;

    int cpb = cg * 4;
#pragma unroll
    for (int k = 0; k < 32; k++) {
        unsigned long long xk;
        asm("mov.b64 %0, {%1,%1};" : "=l"(xk) : "f"(x[k]));
        ulonglong2 w0 = *reinterpret_cast<const ulonglong2*>(&Ws[k][cpb]);
        ulonglong2 w1 = *reinterpret_cast<const ulonglong2*>(&Ws[k][cpb + 2]);
        asm("fma.rn.f32x2 %0, %1, %2, %0;" : "+l"(acc[0]) : "l"(xk), "l"(w0.x));
        asm("fma.rn.f32x2 %0, %1, %2, %0;" : "+l"(acc[1]) : "l"(xk), "l"(w0.y));
        asm("fma.rn.f32x2 %0, %1, %2, %0;" : "+l"(acc[2]) : "l"(xk), "l"(w1.x));
        asm("fma.rn.f32x2 %0, %1, %2, %0;" : "+l"(acc[3]) : "l"(xk), "l"(w1.y));
    }

    unsigned long long d2;
    asm("mov.b64 %0, {%1,%1};" : "=l"(d2) : "f"(di));
    float o[8];
#pragma unroll
    for (int j = 0; j < 4; j++) {
        asm("mul.rn.f32x2 %0, %0, %1;" : "+l"(acc[j]) : "l"(d2));
        asm("mov.b64 {%0,%1}, %2;"
            : "=f"(o[2 * j]), "=f"(o[2 * j + 1]) : "l"(acc[j]));
    }

    // fp32 seed (self-loop term, unquantized)
    size_t base = (size_t)row * 8 + cg * 2;
    g_agg[base]     = make_float4(o[0], o[1], o[2], o[3]);
    g_agg[base + 1] = make_float4(o[4], o[5], o[6], o[7]);

    // fp16 gather payload (bit-cast half2 -> u32 via reinterpret)
    __half2 h0 = __floats2half2_rn(o[0], o[1]);
    __half2 h1 = __floats2half2_rn(o[2], o[3]);
    __half2 h2 = __floats2half2_rn(o[4], o[5]);
    __half2 h3 = __floats2half2_rn(o[6], o[7]);
    uint2 p0, p1;
    p0.x = *reinterpret_cast<unsigned int*>(&h0);
    p0.y = *reinterpret_cast<unsigned int*>(&h1);
    p1.x = *reinterpret_cast<unsigned int*>(&h2);
    p1.y = *reinterpret_cast<unsigned int*>(&h3);
    g_t16[base]     = p0;
    g_t16[base + 1] = p1;
}

// ---------------------------------------------------------------------------
// AGG[dst] += T16[src]  (fp16 gather, fp32 vector reduction).
// Warp owns 32 edges: indices front-loaded (2 coalesced LDG wavefronts /
// 32 edges), SHFL-distributed. 8 independent iterations x 4 edges x 8 lanes;
// lanes 8k..8k+7 cover one edge's 64B fp16 row (LDG.64) and its 128B fp32
// accumulator row (RED.128).
__global__ void k_scatter(const int* __restrict__ src,
                          const int* __restrict__ dst, int E) {
    int warp = (blockIdx.x * blockDim.x + threadIdx.x) >> 5;
    int lane = threadIdx.x & 31;
    int base = warp * 32;
    if (base >= E) return;

    int e = base + lane;
    int sreg = (e < E) ? __ldg(&src[e]) : 0;
    int dreg = (e < E) ? __ldg(&dst[e]) : 0;

    int c   = lane & 7;      // channel quad within row
    int sub = lane >> 3;     // which of 4 edges this iteration

    if (base + 32 <= E) {
#pragma unroll
        for (int it = 0; it < 8; it++) {
            int eloc = it * 4 + sub;
            int s = __shfl_sync(0xffffffff, sreg, eloc);
            int d = __shfl_sync(0xffffffff, dreg, eloc);
            uint2 pv = g_t16[(size_t)s * 8 + c];
            __half2 ha = *reinterpret_cast<__half2*>(&pv.x);
            __half2 hb = *reinterpret_cast<__half2*>(&pv.y);
            float2 f0 = __half22float2(ha);
            float2 f1 = __half22float2(hb);
            float4* p = g_agg + (size_t)d * 8 + c;
            asm volatile("red.global.add.v4.f32 [%0], {%1,%2,%3,%4};"
                         :: "l"(p), "f"(f0.x), "f"(f0.y), "f"(f1.x), "f"(f1.y)
                         : "memory");
        }
    } else {
#pragma unroll
        for (int it = 0; it < 8; it++) {
            int eloc = it * 4 + sub;
            int s = __shfl_sync(0xffffffff, sreg, eloc);
            int d = __shfl_sync(0xffffffff, dreg, eloc);
            if (base + eloc < E) {
                uint2 pv = g_t16[(size_t)s * 8 + c];
                __half2 ha = *reinterpret_cast<__half2*>(&pv.x);
                __half2 hb = *reinterpret_cast<__half2*>(&pv.y);
                float2 f0 = __half22float2(ha);
                float2 f1 = __half22float2(hb);
                float4* p = g_agg + (size_t)d * 8 + c;
                asm volatile("red.global.add.v4.f32 [%0], {%1,%2,%3,%4};"
                             :: "l"(p), "f"(f0.x), "f"(f0.y), "f"(f1.x), "f"(f1.y)
                             : "memory");
            }
        }
    }
}

// ---------------------------------------------------------------------------
// final: mu -> out[0:N*16], logvar -> out[N*16:]
// out = dinv * agg + bias   (agg already contains self-loop term)
__global__ void k_post2(const float* __restrict__ bmu,
                        const float* __restrict__ blv,
                        float* __restrict__ out, int n) {
    int gid = blockIdx.x * blockDim.x + threadIdx.x;
    int i = gid >> 3;
    if (i >= n) return;
    int c = gid & 7;
    float di = rsqrtf(g_degf[i]);
    float4 a = g_agg[(size_t)i * 8 + c];
    float4 r;
    if (c < 4) {
        float4 bb = ((const float4*)bmu)[c];
        r.x = fmaf(di, a.x, bb.x);
        r.y = fmaf(di, a.y, bb.y);
        r.z = fmaf(di, a.z, bb.z);
        r.w = fmaf(di, a.w, bb.w);
        ((float4*)out)[(size_t)i * 4 + c] = r;
    } else {
        float4 bb = ((const float4*)blv)[c - 4];
        r.x = fmaf(di, a.x, bb.x);
        r.y = fmaf(di, a.y, bb.y);
        r.z = fmaf(di, a.z, bb.z);
        r.w = fmaf(di, a.w, bb.w);
        ((float4*)(out + (size_t)n * 16))[(size_t)i * 4 + (c - 4)] = r;
    }
}

// ---------------------------------------------------------------------------
extern "C" void kernel_launch(void* const* d_in, const int* in_sizes, int n_in,
                              void* d_out, int out_size) {
    const float* x   = (const float*)d_in[0];
    const int*   ei  = (const int*)d_in[1];
    const float* W1  = (const float*)d_in[2];
    const float* b1  = (const float*)d_in[3];
    const float* Wmu = (const float*)d_in[4];
    const float* bmu = (const float*)d_in[5];
    const float* Wlv = (const float*)d_in[6];
    const float* blv = (const float*)d_in[7];
    float* out = (float*)d_out;

    int N = in_sizes[0] / 32;
    int E = in_sizes[1] / 2;
    const int* src = ei;          // edge_index row 0
    const int* dst = ei + E;      // edge_index row 1

    const int TB = 256;
    int gN  = (N + TB - 1) / TB;
    int gE  = (E + TB - 1) / TB;
    int gN4 = (int)(((long long)N * 4 + TB - 1) / TB);   // gemm: 4 thr/row
    int gN8 = (int)(((long long)N * 8 + TB - 1) / TB);
    int gEw = (int)(((long long)E + TB - 1) / TB);       // 32 edges per warp

    // degrees (dinv computed inline via rsqrtf where needed)
    k_init<<<gN, TB>>>(N);
    k_deg <<<gE, TB>>>(dst, E);

    // layer 1: t1 -> g_t16 (fp16) + g_agg seed (fp32); scatter adds neighbors
    k_gemm   <<<gN4, TB>>>((const float4*)x, W1, nullptr, nullptr, N);
    k_scatter<<<gEw, TB>>>(src, dst, E);

    // layer 2: fused relu(dinv*agg + b1) -> GEMM(mu|lv) -> re-seed
    k_gemm   <<<gN4, TB>>>(nullptr, Wmu, Wlv, b1, N);
    k_scatter<<<gEw, TB>>>(src, dst, E);

    // final bias + dinv scale, split mu / logvar
    k_post2<<<gN8, TB>>>(bmu, blv, out, N);
}